// round 9
// baseline (speedup 1.0000x reference)
#include <cuda_runtime.h>
#include <cuda_bf16.h>
#include <cstdint>

#define BDIM 2
#define LNUM 6
#define CDIM 128
#define NDIM 4096
#define NT 32
#define NTP 64                       // n-tiles of 64 rows for psum partials
#define BL (BDIM*LNUM)
#define INV_SQRT (1.0f/64.0f)

// ---------------- scratch (static device memory; allocation-free) ----------
__device__ __nv_bfloat16 g_Xt[(size_t)BDIM*NDIM*CDIM];  // [b][n][c] bf16
__device__ __nv_bfloat16 g_Wb[(size_t)3*LNUM*CDIM*CDIM];// [p][l][o][c] bf16
__device__ __nv_bfloat16 g_Qb[(size_t)BL*NDIM*CDIM];    // [bl][n][c]
__device__ __nv_bfloat16 g_Kb[(size_t)BL*NDIM*CDIM];    // [bl][m][c]
__device__ __nv_bfloat16 g_Gt[(size_t)BL*CDIM*NDIM];    // [bl][c][m] (alpha folded in by scale_kernel)
__device__ __nv_bfloat16 g_Sb[(size_t)BL*NDIM*NDIM];    // [bl][n][m] e = exp(s/64)
__device__ float g_psum[(size_t)BL*NDIM*NTP];           // partial sum_n e per (m, ntile64)
__device__ float g_alpha[(size_t)BL*NDIM];              // 1/Z per m
__device__ float g_acc[(size_t)BL*2*CDIM*NDIM];         // per-(layer,split) output [c][n]

// ---------------- helpers ----------------------------------------------------
__device__ __forceinline__ uint32_t smem_u32(const void* p) {
    uint32_t a;
    asm("{ .reg .u64 t; cvta.to.shared.u64 t, %1; cvt.u32.u64 %0, t; }" : "=r"(a) : "l"(p));
    return a;
}

// swizzled byte offset inside [rows][256B] tile: chunk = 16B unit (0..15)
__device__ __forceinline__ uint32_t SWZ(int row, int chunk) {
    return (uint32_t)row * 256u + (uint32_t)((chunk ^ (row & 7)) << 4);
}
// swizzled byte offset inside [rows][128B] tile: chunk = 16B unit (0..7)
__device__ __forceinline__ uint32_t SWZ8(int row, int chunk) {
    return (uint32_t)row * 128u + (uint32_t)((chunk ^ (row & 7)) << 4);
}

__device__ __forceinline__ void ldmx4(uint32_t* r, uint32_t addr) {
    asm volatile("ldmatrix.sync.aligned.m8n8.x4.shared.b16 {%0,%1,%2,%3}, [%4];"
        : "=r"(r[0]), "=r"(r[1]), "=r"(r[2]), "=r"(r[3]) : "r"(addr));
}

__device__ __forceinline__ void mma16816(float* d, const uint32_t* a, uint32_t b0, uint32_t b1) {
    asm volatile("mma.sync.aligned.m16n8k16.row.col.f32.bf16.bf16.f32 "
        "{%0,%1,%2,%3}, {%4,%5,%6,%7}, {%8,%9}, {%0,%1,%2,%3};"
        : "+f"(d[0]), "+f"(d[1]), "+f"(d[2]), "+f"(d[3])
        : "r"(a[0]), "r"(a[1]), "r"(a[2]), "r"(a[3]), "r"(b0), "r"(b1));
}

#define CP_ASYNC16(dst, src) \
    asm volatile("cp.async.cg.shared.global [%0], [%1], 16;" :: "r"(dst), "l"(src))
#define CP_COMMIT() asm volatile("cp.async.commit_group;" ::: "memory")
#define CP_WAIT(n)  asm volatile("cp.async.wait_group %0;" :: "n"(n) : "memory")

// ---------------- kernel 0a: X -> Xt bf16 (transpose) -----------------------
__global__ void xt_kernel(const float* __restrict__ X)
{
    __shared__ float t[32][33];
    int b = blockIdx.z, c0 = blockIdx.y * 32, n0 = blockIdx.x * 32;
    int tx = threadIdx.x, ty = threadIdx.y;   // 32 x 8
    const float* Xb = X + (size_t)b * CDIM * NDIM;
    #pragma unroll
    for (int i = 0; i < 4; i++)
        t[ty + 8 * i][tx] = Xb[(size_t)(c0 + ty + 8 * i) * NDIM + n0 + tx];
    __syncthreads();
    __nv_bfloat16* dst = g_Xt + (size_t)b * NDIM * CDIM;
    #pragma unroll
    for (int i = 0; i < 4; i++)
        dst[(size_t)(n0 + ty + 8 * i) * CDIM + c0 + tx] = __float2bfloat16(t[tx][ty + 8 * i]);
}

// ---------------- kernel 0b: weights -> bf16 --------------------------------
__global__ void wcvt_kernel(const float* __restrict__ W1, const float* __restrict__ W2,
                            const float* __restrict__ Wg)
{
    int idx = blockIdx.x * blockDim.x + threadIdx.x;
    const int per = LNUM * CDIM * CDIM;
    if (idx >= 3 * per) return;
    const float* src = (idx < per) ? W1 : (idx < 2 * per) ? W2 : Wg;
    g_Wb[idx] = __float2bfloat16(src[idx % per]);
}

// ---------------- kernel 1: projections via mma.sync ------------------------
#define SMEM_PROJ 65536
__global__ __launch_bounds__(256) void projmma_kernel(const float* __restrict__ b1,
                                                      const float* __restrict__ b2,
                                                      const float* __restrict__ bg)
{
    extern __shared__ char sm[];
    uint32_t sbA = smem_u32(sm);
    uint32_t sbB = sbA + 32768;

    int tid = threadIdx.x, lane = tid & 31, w = tid >> 5;
    int wn = w >> 2, wm = w & 3;                 // 2(row) x 4(col) warp grid
    int bl = blockIdx.z, p = blockIdx.y, n0 = blockIdx.x * 128;
    int b = bl / LNUM, l = bl % LNUM;

    const __nv_bfloat16* Xp = g_Xt + ((size_t)b * NDIM + n0) * CDIM;
    const __nv_bfloat16* Wp = g_Wb + (size_t)(p * LNUM + l) * CDIM * CDIM;
    const float* bias = ((p == 0) ? b1 : (p == 1) ? b2 : bg) + l * CDIM;

    const __nv_bfloat16* Ap = (p < 2) ? Xp : Wp;
    const __nv_bfloat16* Bp = (p < 2) ? Wp : Xp;

    #pragma unroll
    for (int it = 0; it < 8; it++) {
        int s = tid + it * 256;
        int row = s >> 4, ch = s & 15;
        CP_ASYNC16(sbA + SWZ(row, ch), Ap + (size_t)row * CDIM + ch * 8);
        CP_ASYNC16(sbB + SWZ(row, ch), Bp + (size_t)row * CDIM + ch * 8);
    }
    CP_COMMIT();
    CP_WAIT(0);
    __syncthreads();

    float acc[4][4][4];
    #pragma unroll
    for (int i = 0; i < 4; i++)
        #pragma unroll
        for (int j = 0; j < 4; j++)
            #pragma unroll
            for (int q = 0; q < 4; q++) acc[i][j][q] = 0.f;

    #pragma unroll
    for (int ks = 0; ks < 8; ks++) {
        uint32_t a[4][4], bfrag[2][4];
        #pragma unroll
        for (int mi = 0; mi < 4; mi++)
            ldmx4(a[mi], sbA + SWZ(wn * 64 + mi * 16 + (lane & 15), 2 * ks + (lane >> 4)));
        #pragma unroll
        for (int q = 0; q < 2; q++)
            ldmx4(bfrag[q], sbB + SWZ(wm * 32 + q * 16 + (lane & 7) + ((lane >> 4) << 3),
                                      2 * ks + ((lane >> 3) & 1)));
        #pragma unroll
        for (int mi = 0; mi < 4; mi++)
            #pragma unroll
            for (int q = 0; q < 2; q++) {
                mma16816(acc[mi][2 * q],     a[mi], bfrag[q][0], bfrag[q][1]);
                mma16816(acc[mi][2 * q + 1], a[mi], bfrag[q][2], bfrag[q][3]);
            }
    }

    int gid = lane >> 2, tig = lane & 3;
    __syncthreads();   // all warps done reading operand smem; reuse sbA as out-tile

    #pragma unroll
    for (int mi = 0; mi < 4; mi++) {
        int r0 = wn * 64 + mi * 16 + gid;
        float brow0 = 0.f, brow8 = 0.f;
        if (p == 2) { brow0 = bias[r0]; brow8 = bias[r0 + 8]; }
        #pragma unroll
        for (int nj = 0; nj < 4; nj++) {
            int mc = wm * 32 + nj * 8 + 2 * tig;
            float v0 = acc[mi][nj][0], v1 = acc[mi][nj][1];
            float v2 = acc[mi][nj][2], v3 = acc[mi][nj][3];
            if (p < 2) {
                float bc0 = bias[mc], bc1 = bias[mc + 1];
                v0 += bc0; v1 += bc1; v2 += bc0; v3 += bc1;
            } else {
                v0 += brow0; v1 += brow0; v2 += brow8; v3 += brow8;
            }
            __nv_bfloat162 h01, h23;
            h01.x = __float2bfloat16(v0); h01.y = __float2bfloat16(v1);
            h23.x = __float2bfloat16(v2); h23.y = __float2bfloat16(v3);
            int chn = wm * 4 + nj;
            *(__nv_bfloat162*)(sm + SWZ(r0, chn) + tig * 4)     = h01;
            *(__nv_bfloat162*)(sm + SWZ(r0 + 8, chn) + tig * 4) = h23;
        }
    }
    __syncthreads();

    if (p < 2) {
        __nv_bfloat16* dst = (p == 0 ? g_Qb : g_Kb) + ((size_t)bl * NDIM + n0) * CDIM;
        #pragma unroll
        for (int it = 0; it < 8; it++) {
            int s = tid + it * 256;
            int row = s >> 4, ch = s & 15;
            *(uint4*)(dst + (size_t)row * CDIM + ch * 8) = *(uint4*)(sm + SWZ(row, ch));
        }
    } else {
        __nv_bfloat16* dst = g_Gt + (size_t)bl * CDIM * NDIM;
        #pragma unroll
        for (int it = 0; it < 8; it++) {
            int s = tid + it * 256;
            int row = s >> 4, ch = s & 15;
            *(uint4*)(dst + (size_t)row * NDIM + n0 + ch * 8) = *(uint4*)(sm + SWZ(row, ch));
        }
    }
}

// ---------------- kernel 2: scores v3 — 128-thr CTAs, 4/SM, Q-resident ------
// CTA tile 64n x 128m; warp grid 2(n) x 2(m), warp tile 32x64.
// smem: Q 16KB | K 32KB (reused as e-tile) | red 1KB  => 49KB, 4 CTA/SM.
#define SMEM_SCORE (49152 + 1024)
__global__ __launch_bounds__(128, 4) void score_kernel()
{
    extern __shared__ char sm[];
    uint32_t sbQ = smem_u32(sm);
    uint32_t sbK = sbQ + 16384;
    char*    smK = sm + 16384;
    float* red = (float*)(sm + 49152);

    int tid = threadIdx.x, lane = tid & 31, w = tid >> 5;
    int wn = w >> 1, wm = w & 1;                 // 2(n) x 2(m) warp grid
    int bl = blockIdx.z, n0 = blockIdx.x * 64, mg = blockIdx.y * 1024;

    const __nv_bfloat16* Qp = g_Qb + (size_t)bl * NDIM * CDIM;
    const __nv_bfloat16* Kp = g_Kb + (size_t)bl * NDIM * CDIM;
    __nv_bfloat16* Sp = g_Sb + (size_t)bl * NDIM * NDIM;

    int lrow = tid >> 4, lch = tid & 15;         // loader: 8 rows x 16 chunks per it

    // Q tile (64 rows), loaded once
    #pragma unroll
    for (int it = 0; it < 8; it++) {
        int row = lrow + it * 8;
        CP_ASYNC16(sbQ + SWZ(row, lch), Qp + (size_t)(n0 + row) * CDIM + lch * 8);
    }
    CP_COMMIT();

    int gid = lane >> 2, tig = lane & 3;

    for (int mi = 0; mi < 8; mi++) {
        int m0 = mg + mi * 128;
        // K tile (128 rows)
        #pragma unroll
        for (int it = 0; it < 16; it++) {
            int row = lrow + it * 8;
            CP_ASYNC16(sbK + SWZ(row, lch), Kp + (size_t)(m0 + row) * CDIM + lch * 8);
        }
        CP_COMMIT();
        CP_WAIT(0);
        __syncthreads();

        float acc[2][8][4];
        #pragma unroll
        for (int i = 0; i < 2; i++)
            #pragma unroll
            for (int j = 0; j < 8; j++)
                #pragma unroll
                for (int q = 0; q < 4; q++) acc[i][j][q] = 0.f;

        #pragma unroll
        for (int ks = 0; ks < 8; ks++) {
            uint32_t a[2][4], b[4][4];
            #pragma unroll
            for (int ai = 0; ai < 2; ai++)
                ldmx4(a[ai], sbQ + SWZ(wn * 32 + ai * 16 + (lane & 15), 2 * ks + (lane >> 4)));
            #pragma unroll
            for (int bi = 0; bi < 4; bi++)
                ldmx4(b[bi], sbK + SWZ(wm * 64 + bi * 16 + (lane & 7) + ((lane >> 4) << 3),
                                       2 * ks + ((lane >> 3) & 1)));
            #pragma unroll
            for (int ai = 0; ai < 2; ai++)
                #pragma unroll
                for (int bi = 0; bi < 4; bi++) {
                    mma16816(acc[ai][2 * bi],     a[ai], b[bi][0], b[bi][1]);
                    mma16816(acc[ai][2 * bi + 1], a[ai], b[bi][2], b[bi][3]);
                }
        }
        __syncthreads();            // all warps done reading K; reuse as e-tile

        float ss[8][2];
        #pragma unroll
        for (int nj = 0; nj < 8; nj++) { ss[nj][0] = 0.f; ss[nj][1] = 0.f; }

        #pragma unroll
        for (int ai = 0; ai < 2; ai++) {
            int r0 = wn * 32 + ai * 16 + gid;
            #pragma unroll
            for (int nj = 0; nj < 8; nj++) {
                float e0 = __expf(acc[ai][nj][0] * INV_SQRT);
                float e1 = __expf(acc[ai][nj][1] * INV_SQRT);
                float e2 = __expf(acc[ai][nj][2] * INV_SQRT);
                float e3 = __expf(acc[ai][nj][3] * INV_SQRT);
                __nv_bfloat162 h01, h23;
                h01.x = __float2bfloat16(e0); h01.y = __float2bfloat16(e1);
                h23.x = __float2bfloat16(e2); h23.y = __float2bfloat16(e3);
                int chn = wm * 8 + nj;
                *(__nv_bfloat162*)(smK + SWZ(r0, chn) + tig * 4)     = h01;
                *(__nv_bfloat162*)(smK + SWZ(r0 + 8, chn) + tig * 4) = h23;
                ss[nj][0] += __bfloat162float(h01.x) + __bfloat162float(h23.x);
                ss[nj][1] += __bfloat162float(h01.y) + __bfloat162float(h23.y);
            }
        }

        #pragma unroll
        for (int nj = 0; nj < 8; nj++) {
            #pragma unroll
            for (int off = 4; off < 32; off <<= 1) {
                ss[nj][0] += __shfl_xor_sync(0xffffffffu, ss[nj][0], off);
                ss[nj][1] += __shfl_xor_sync(0xffffffffu, ss[nj][1], off);
            }
        }
        if (lane < 4) {
            #pragma unroll
            for (int nj = 0; nj < 8; nj++) {
                red[wn * 128 + wm * 64 + nj * 8 + 2 * tig]     = ss[nj][0];
                red[wn * 128 + wm * 64 + nj * 8 + 2 * tig + 1] = ss[nj][1];
            }
        }
        __syncthreads();            // e-tile + red complete

        // coalesced Sb store (64 rows x 128 cols bf16)
        #pragma unroll
        for (int it = 0; it < 8; it++) {
            int row = lrow + it * 8;
            *(uint4*)(Sp + (size_t)(n0 + row) * NDIM + m0 + lch * 8) =
                *(uint4*)(smK + SWZ(row, lch));
        }
        g_psum[((size_t)bl * NDIM + m0 + tid) * NTP + blockIdx.x] = red[tid] + red[128 + tid];

        __syncthreads();            // K/e buffer free before next cp.async
    }
}

// ---------------- kernel 3: alpha = 1/Z -------------------------------------
__global__ void stats_kernel()
{
    int idx = blockIdx.x * blockDim.x + threadIdx.x;
    if (idx >= BL * NDIM) return;
    const float* ps = g_psum + (size_t)idx * NTP;
    float Z = 0.f;
    #pragma unroll
    for (int t = 0; t < NTP; t++) Z += ps[t];
    g_alpha[idx] = 1.f / Z;
}

// ---------------- kernel 3b: fold alpha into Gt (in place) ------------------
__global__ void scale_kernel()
{
    size_t v = (size_t)blockIdx.x * blockDim.x + threadIdx.x;     // uint4 index
    const size_t nvec = (size_t)BL * CDIM * NDIM / 8;
    if (v >= nvec) return;
    size_t e0 = v * 8;
    size_t bl = e0 / ((size_t)CDIM * NDIM);
    size_t m  = e0 % NDIM;
    const float* al = g_alpha + bl * NDIM + m;
    uint4 u = *(uint4*)(g_Gt + e0);
    __nv_bfloat162* h = (__nv_bfloat162*)&u;
    #pragma unroll
    for (int j = 0; j < 4; j++) {
        float2 f = __bfloat1622float2(h[j]);
        h[j].x = __float2bfloat16(f.x * al[2 * j]);
        h[j].y = __float2bfloat16(f.y * al[2 * j + 1]);
    }
    *(uint4*)(g_Gt + e0) = u;
}

// ---------------- kernel 4: acc[c][n] = sum_m Gta[c][m] * e[n][m] ------------
#define KC 64
#define NC 32
#define STG_BYTES 32768
#define SMEM_ATT (3 * STG_BYTES)
__global__ __launch_bounds__(256, 2) void attnout_kernel()
{
    extern __shared__ char sm[];
    uint32_t sb = smem_u32(sm);

    int tid = threadIdx.x, lane = tid & 31, w = tid >> 5;
    int wc = w >> 2, wn = w & 3;
    int bl = blockIdx.y, n0 = blockIdx.x * 128;
    int mbase = blockIdx.z * 2048;

    const __nv_bfloat16* Gp = g_Gt + (size_t)bl * CDIM * NDIM;
    const __nv_bfloat16* Sp = g_Sb + (size_t)bl * NDIM * NDIM;

    int lrow = tid >> 3, lch = tid & 7;

    #pragma unroll
    for (int p = 0; p < 3; p++) {
        int mq = mbase + p * KC;
        uint32_t sA = sb + p * STG_BYTES, sB = sA + 16384;
        #pragma unroll
        for (int it = 0; it < 4; it++) {
            int row = lrow + it * 32;
            CP_ASYNC16(sA + SWZ8(row, lch), Gp + (size_t)row * NDIM + mq + lch * 8);
            CP_ASYNC16(sB + SWZ8(row, lch), Sp + (size_t)(n0 + row) * NDIM + mq + lch * 8);
        }
        CP_COMMIT();
    }

    float acc[4][4][4];
    #pragma unroll
    for (int i = 0; i < 4; i++)
        #pragma unroll
        for (int j = 0; j < 4; j++)
            #pragma unroll
            for (int q = 0; q < 4; q++) acc[i][j][q] = 0.f;

    int st = 0;
    for (int chk = 0; chk < NC; chk++) {
        CP_WAIT(2);
        __syncthreads();

        uint32_t sA = sb + st * STG_BYTES, sB = sA + 16384;
        #pragma unroll
        for (int ks = 0; ks < 4; ks++) {
            uint32_t a[4][4], b[2][4];
            #pragma unroll
            for (int mi = 0; mi < 4; mi++)
                ldmx4(a[mi], sA + SWZ8(wc * 64 + mi * 16 + (lane & 15), 2 * ks + (lane >> 4)));
            #pragma unroll
            for (int q = 0; q < 2; q++)
                ldmx4(b[q], sB + SWZ8(wn * 32 + q * 16 + (lane & 7) + ((lane >> 4) << 3),
                                      2 * ks + ((lane >> 3) & 1)));
            #pragma unroll
            for (int mi = 0; mi < 4; mi++)
                #pragma unroll
                for (int q = 0; q < 2; q++) {
                    mma16816(acc[mi][2 * q],     a[mi], b[q][0], b[q][1]);
                    mma16816(acc[mi][2 * q + 1], a[mi], b[q][2], b[q][3]);
                }
        }
        __syncthreads();

        if (chk + 3 < NC) {
            int mq = mbase + (chk + 3) * KC;
            #pragma unroll
            for (int it = 0; it < 4; it++) {
                int row = lrow + it * 32;
                CP_ASYNC16(sA + SWZ8(row, lch), Gp + (size_t)row * NDIM + mq + lch * 8);
                CP_ASYNC16(sB + SWZ8(row, lch), Sp + (size_t)(n0 + row) * NDIM + mq + lch * 8);
            }
        }
        CP_COMMIT();
        st = (st + 1 == 3) ? 0 : st + 1;
    }

    int gid = lane >> 2, tig = lane & 3;
    float* dstb = g_acc + ((size_t)(bl * 2 + blockIdx.z)) * CDIM * NDIM;
    #pragma unroll
    for (int mi = 0; mi < 4; mi++) {
        int c0 = wc * 64 + mi * 16 + gid;
        #pragma unroll
        for (int nj = 0; nj < 4; nj++) {
            int n = n0 + wn * 32 + nj * 8 + 2 * tig;
            *(float2*)(dstb + (size_t)c0 * NDIM + n)       = make_float2(acc[mi][nj][0], acc[mi][nj][1]);
            *(float2*)(dstb + (size_t)(c0 + 8) * NDIM + n) = make_float2(acc[mi][nj][2], acc[mi][nj][3]);
        }
    }
}

// ---------------- kernel 5: out = x + mean_l(acc) ---------------------------
__global__ void epilogue_kernel(const float* __restrict__ X, float* __restrict__ out)
{
    size_t idx = (size_t)blockIdx.x * blockDim.x + threadIdx.x;
    const size_t total = (size_t)BDIM * CDIM * NDIM;
    if (idx >= total) return;
    size_t b   = idx / ((size_t)CDIM * NDIM);
    size_t rem = idx % ((size_t)CDIM * NDIM);
    float s = 0.f;
    #pragma unroll
    for (int l = 0; l < LNUM; l++) {
        size_t base = ((size_t)(b * LNUM + l) * 2) * CDIM * NDIM;
        s += g_acc[base + rem] + g_acc[base + (size_t)CDIM * NDIM + rem];
    }
    out[idx] = X[idx] + s * (1.0f / LNUM);
}

// ---------------- launch -----------------------------------------------------
extern "C" void kernel_launch(void* const* d_in, const int* in_sizes, int n_in,
                              void* d_out, int out_size)
{
    const float* x  = (const float*)d_in[0];
    const float* W1 = (const float*)d_in[1];
    const float* b1 = (const float*)d_in[2];
    const float* W2 = (const float*)d_in[3];
    const float* b2 = (const float*)d_in[4];
    const float* Wg = (const float*)d_in[5];
    const float* bg = (const float*)d_in[6];
    float* out = (float*)d_out;

    cudaFuncSetAttribute(projmma_kernel, cudaFuncAttributeMaxDynamicSharedMemorySize, SMEM_PROJ);
    cudaFuncSetAttribute(score_kernel,   cudaFuncAttributeMaxDynamicSharedMemorySize, SMEM_SCORE);
    cudaFuncSetAttribute(attnout_kernel, cudaFuncAttributeMaxDynamicSharedMemorySize, SMEM_ATT);

    xt_kernel<<<dim3(NDIM / 32, CDIM / 32, BDIM), dim3(32, 8)>>>(x);
    wcvt_kernel<<<(3 * LNUM * CDIM * CDIM + 255) / 256, 256>>>(W1, W2, Wg);
    projmma_kernel<<<dim3(NT, 3, BL), 256, SMEM_PROJ>>>(b1, b2, bg);
    score_kernel<<<dim3(NTP, 4, BL), 128, SMEM_SCORE>>>();
    stats_kernel<<<(BL * NDIM + 255) / 256, 256>>>();
    scale_kernel<<<(unsigned)(((size_t)BL * CDIM * NDIM / 8 + 255) / 256), 256>>>();
    attnout_kernel<<<dim3(NT, BL, 2), 256, SMEM_ATT>>>();
    epilogue_kernel<<<(unsigned)(((size_t)BDIM * CDIM * NDIM + 255) / 256), 256>>>(x, out);
}

// round 10
// speedup vs baseline: 1.0149x; 1.0149x over previous
#include <cuda_runtime.h>
#include <cuda_bf16.h>
#include <cstdint>

#define BDIM 2
#define LNUM 6
#define CDIM 128
#define NDIM 4096
#define NT 32
#define NTP 64                       // n-tiles of 64 rows for psum partials
#define BL (BDIM*LNUM)
#define INV_SQRT (1.0f/64.0f)

// ---------------- scratch (static device memory; allocation-free) ----------
__device__ __nv_bfloat16 g_Xt[(size_t)BDIM*NDIM*CDIM];  // [b][n][c] bf16
__device__ __nv_bfloat16 g_Wb[(size_t)3*LNUM*CDIM*CDIM];// [p][l][o][c] bf16
__device__ __nv_bfloat16 g_Qb[(size_t)BL*NDIM*CDIM];    // [bl][n][c]
__device__ __nv_bfloat16 g_Kb[(size_t)BL*NDIM*CDIM];    // [bl][m][c]
__device__ __nv_bfloat16 g_Gt[(size_t)BL*CDIM*NDIM];    // [bl][c][m] (alpha folded in by scale_kernel)
__device__ __nv_bfloat16 g_Sb[(size_t)BL*NDIM*NDIM];    // [bl][n][m] e = exp(s/64)
__device__ float g_psum[(size_t)BL*NDIM*NTP];           // partial sum_n e per (m, ntile64)
__device__ float g_alpha[(size_t)BL*NDIM];              // 1/Z per m
__device__ float g_acc[(size_t)BL*2*CDIM*NDIM];         // per-(layer,split) output [c][n]

// ---------------- helpers ----------------------------------------------------
__device__ __forceinline__ uint32_t smem_u32(const void* p) {
    uint32_t a;
    asm("{ .reg .u64 t; cvta.to.shared.u64 t, %1; cvt.u32.u64 %0, t; }" : "=r"(a) : "l"(p));
    return a;
}

// swizzled byte offset inside [rows][256B] tile: chunk = 16B unit (0..15)
__device__ __forceinline__ uint32_t SWZ(int row, int chunk) {
    return (uint32_t)row * 256u + (uint32_t)((chunk ^ (row & 7)) << 4);
}
// swizzled byte offset inside [rows][128B] tile: chunk = 16B unit (0..7)
__device__ __forceinline__ uint32_t SWZ8(int row, int chunk) {
    return (uint32_t)row * 128u + (uint32_t)((chunk ^ (row & 7)) << 4);
}

__device__ __forceinline__ void ldmx4(uint32_t* r, uint32_t addr) {
    asm volatile("ldmatrix.sync.aligned.m8n8.x4.shared.b16 {%0,%1,%2,%3}, [%4];"
        : "=r"(r[0]), "=r"(r[1]), "=r"(r[2]), "=r"(r[3]) : "r"(addr));
}

__device__ __forceinline__ void mma16816(float* d, const uint32_t* a, uint32_t b0, uint32_t b1) {
    asm volatile("mma.sync.aligned.m16n8k16.row.col.f32.bf16.bf16.f32 "
        "{%0,%1,%2,%3}, {%4,%5,%6,%7}, {%8,%9}, {%0,%1,%2,%3};"
        : "+f"(d[0]), "+f"(d[1]), "+f"(d[2]), "+f"(d[3])
        : "r"(a[0]), "r"(a[1]), "r"(a[2]), "r"(a[3]), "r"(b0), "r"(b1));
}

#define CP_ASYNC16(dst, src) \
    asm volatile("cp.async.cg.shared.global [%0], [%1], 16;" :: "r"(dst), "l"(src))
#define CP_COMMIT() asm volatile("cp.async.commit_group;" ::: "memory")
#define CP_WAIT(n)  asm volatile("cp.async.wait_group %0;" :: "n"(n) : "memory")

// ---------------- kernel 0a: X -> Xt bf16 (transpose) -----------------------
__global__ void xt_kernel(const float* __restrict__ X)
{
    __shared__ float t[32][33];
    int b = blockIdx.z, c0 = blockIdx.y * 32, n0 = blockIdx.x * 32;
    int tx = threadIdx.x, ty = threadIdx.y;   // 32 x 8
    const float* Xb = X + (size_t)b * CDIM * NDIM;
    #pragma unroll
    for (int i = 0; i < 4; i++)
        t[ty + 8 * i][tx] = Xb[(size_t)(c0 + ty + 8 * i) * NDIM + n0 + tx];
    __syncthreads();
    __nv_bfloat16* dst = g_Xt + (size_t)b * NDIM * CDIM;
    #pragma unroll
    for (int i = 0; i < 4; i++)
        dst[(size_t)(n0 + ty + 8 * i) * CDIM + c0 + tx] = __float2bfloat16(t[tx][ty + 8 * i]);
}

// ---------------- kernel 0b: weights -> bf16 --------------------------------
__global__ void wcvt_kernel(const float* __restrict__ W1, const float* __restrict__ W2,
                            const float* __restrict__ Wg)
{
    int idx = blockIdx.x * blockDim.x + threadIdx.x;
    const int per = LNUM * CDIM * CDIM;
    if (idx >= 3 * per) return;
    const float* src = (idx < per) ? W1 : (idx < 2 * per) ? W2 : Wg;
    g_Wb[idx] = __float2bfloat16(src[idx % per]);
}

// ---------------- kernel 1: projections via mma.sync ------------------------
#define SMEM_PROJ 65536
__global__ __launch_bounds__(256) void projmma_kernel(const float* __restrict__ b1,
                                                      const float* __restrict__ b2,
                                                      const float* __restrict__ bg)
{
    extern __shared__ char sm[];
    uint32_t sbA = smem_u32(sm);
    uint32_t sbB = sbA + 32768;

    int tid = threadIdx.x, lane = tid & 31, w = tid >> 5;
    int wn = w >> 2, wm = w & 3;                 // 2(row) x 4(col) warp grid
    int bl = blockIdx.z, p = blockIdx.y, n0 = blockIdx.x * 128;
    int b = bl / LNUM, l = bl % LNUM;

    const __nv_bfloat16* Xp = g_Xt + ((size_t)b * NDIM + n0) * CDIM;
    const __nv_bfloat16* Wp = g_Wb + (size_t)(p * LNUM + l) * CDIM * CDIM;
    const float* bias = ((p == 0) ? b1 : (p == 1) ? b2 : bg) + l * CDIM;

    const __nv_bfloat16* Ap = (p < 2) ? Xp : Wp;
    const __nv_bfloat16* Bp = (p < 2) ? Wp : Xp;

    #pragma unroll
    for (int it = 0; it < 8; it++) {
        int s = tid + it * 256;
        int row = s >> 4, ch = s & 15;
        CP_ASYNC16(sbA + SWZ(row, ch), Ap + (size_t)row * CDIM + ch * 8);
        CP_ASYNC16(sbB + SWZ(row, ch), Bp + (size_t)row * CDIM + ch * 8);
    }
    CP_COMMIT();
    CP_WAIT(0);
    __syncthreads();

    float acc[4][4][4];
    #pragma unroll
    for (int i = 0; i < 4; i++)
        #pragma unroll
        for (int j = 0; j < 4; j++)
            #pragma unroll
            for (int q = 0; q < 4; q++) acc[i][j][q] = 0.f;

    #pragma unroll
    for (int ks = 0; ks < 8; ks++) {
        uint32_t a[4][4], bfrag[2][4];
        #pragma unroll
        for (int mi = 0; mi < 4; mi++)
            ldmx4(a[mi], sbA + SWZ(wn * 64 + mi * 16 + (lane & 15), 2 * ks + (lane >> 4)));
        #pragma unroll
        for (int q = 0; q < 2; q++)
            ldmx4(bfrag[q], sbB + SWZ(wm * 32 + q * 16 + (lane & 7) + ((lane >> 4) << 3),
                                      2 * ks + ((lane >> 3) & 1)));
        #pragma unroll
        for (int mi = 0; mi < 4; mi++)
            #pragma unroll
            for (int q = 0; q < 2; q++) {
                mma16816(acc[mi][2 * q],     a[mi], bfrag[q][0], bfrag[q][1]);
                mma16816(acc[mi][2 * q + 1], a[mi], bfrag[q][2], bfrag[q][3]);
            }
    }

    int gid = lane >> 2, tig = lane & 3;
    __syncthreads();   // all warps done reading operand smem; reuse sbA as out-tile

    #pragma unroll
    for (int mi = 0; mi < 4; mi++) {
        int r0 = wn * 64 + mi * 16 + gid;
        float brow0 = 0.f, brow8 = 0.f;
        if (p == 2) { brow0 = bias[r0]; brow8 = bias[r0 + 8]; }
        #pragma unroll
        for (int nj = 0; nj < 4; nj++) {
            int mc = wm * 32 + nj * 8 + 2 * tig;
            float v0 = acc[mi][nj][0], v1 = acc[mi][nj][1];
            float v2 = acc[mi][nj][2], v3 = acc[mi][nj][3];
            if (p < 2) {
                float bc0 = bias[mc], bc1 = bias[mc + 1];
                v0 += bc0; v1 += bc1; v2 += bc0; v3 += bc1;
            } else {
                v0 += brow0; v1 += brow0; v2 += brow8; v3 += brow8;
            }
            __nv_bfloat162 h01, h23;
            h01.x = __float2bfloat16(v0); h01.y = __float2bfloat16(v1);
            h23.x = __float2bfloat16(v2); h23.y = __float2bfloat16(v3);
            int chn = wm * 4 + nj;
            *(__nv_bfloat162*)(sm + SWZ(r0, chn) + tig * 4)     = h01;
            *(__nv_bfloat162*)(sm + SWZ(r0 + 8, chn) + tig * 4) = h23;
        }
    }
    __syncthreads();

    if (p < 2) {
        __nv_bfloat16* dst = (p == 0 ? g_Qb : g_Kb) + ((size_t)bl * NDIM + n0) * CDIM;
        #pragma unroll
        for (int it = 0; it < 8; it++) {
            int s = tid + it * 256;
            int row = s >> 4, ch = s & 15;
            *(uint4*)(dst + (size_t)row * CDIM + ch * 8) = *(uint4*)(sm + SWZ(row, ch));
        }
    } else {
        __nv_bfloat16* dst = g_Gt + (size_t)bl * CDIM * NDIM;
        #pragma unroll
        for (int it = 0; it < 8; it++) {
            int s = tid + it * 256;
            int row = s >> 4, ch = s & 15;
            *(uint4*)(dst + (size_t)row * NDIM + n0 + ch * 8) = *(uint4*)(sm + SWZ(row, ch));
        }
    }
}

// ---------------- kernel 2: scores v5 — low-reg 128-thr CTAs, 6/SM ----------
// CTA tile 64n x 64m; warp grid 2(n) x 2(m), warp tile 32x32 (acc = 32 regs).
// Q resident (16KB); loops 8 m-tiles of 64; K buffer (16KB) reused as e-tile.
// smem 33KB, __launch_bounds__(128,6) -> <=85 regs -> 6 CTA/SM = 24 warps.
#define SMEM_SCORE (32768 + 512)
__global__ __launch_bounds__(128, 6) void score_kernel()
{
    extern __shared__ char sm[];
    uint32_t sbQ = smem_u32(sm);
    uint32_t sbK = sbQ + 16384;
    char*    smK = sm + 16384;
    float* red = (float*)(sm + 32768);

    int tid = threadIdx.x, lane = tid & 31, w = tid >> 5;
    int wn = w >> 1, wm = w & 1;                 // 2(n) x 2(m) warp grid
    int bl = blockIdx.z, n0 = blockIdx.x * 64, mg = blockIdx.y * 512;

    const __nv_bfloat16* Qp = g_Qb + (size_t)bl * NDIM * CDIM;
    const __nv_bfloat16* Kp = g_Kb + (size_t)bl * NDIM * CDIM;
    __nv_bfloat16* Sp = g_Sb + (size_t)bl * NDIM * NDIM;

    int lrow = tid >> 4, lch = tid & 15;         // loader: 8 rows x 16 chunks per it

    // Q tile (64 rows x 256B), loaded once
    #pragma unroll
    for (int it = 0; it < 8; it++) {
        int row = lrow + it * 8;
        CP_ASYNC16(sbQ + SWZ(row, lch), Qp + (size_t)(n0 + row) * CDIM + lch * 8);
    }
    CP_COMMIT();

    int gid = lane >> 2, tig = lane & 3;

    for (int mi = 0; mi < 8; mi++) {
        int m0 = mg + mi * 64;
        // K tile (64 rows x 256B)
        #pragma unroll
        for (int it = 0; it < 8; it++) {
            int row = lrow + it * 8;
            CP_ASYNC16(sbK + SWZ(row, lch), Kp + (size_t)(m0 + row) * CDIM + lch * 8);
        }
        CP_COMMIT();
        CP_WAIT(0);
        __syncthreads();

        float acc[2][4][4];
        #pragma unroll
        for (int i = 0; i < 2; i++)
            #pragma unroll
            for (int j = 0; j < 4; j++)
                #pragma unroll
                for (int q = 0; q < 4; q++) acc[i][j][q] = 0.f;

        #pragma unroll
        for (int ks = 0; ks < 8; ks++) {
            uint32_t a[2][4], b[2][4];
            #pragma unroll
            for (int ai = 0; ai < 2; ai++)
                ldmx4(a[ai], sbQ + SWZ(wn * 32 + ai * 16 + (lane & 15), 2 * ks + (lane >> 4)));
            #pragma unroll
            for (int q = 0; q < 2; q++)
                ldmx4(b[q], sbK + SWZ(wm * 32 + q * 16 + (lane & 7) + ((lane >> 4) << 3),
                                      2 * ks + ((lane >> 3) & 1)));
            #pragma unroll
            for (int ai = 0; ai < 2; ai++)
                #pragma unroll
                for (int q = 0; q < 2; q++) {
                    mma16816(acc[ai][2 * q],     a[ai], b[q][0], b[q][1]);
                    mma16816(acc[ai][2 * q + 1], a[ai], b[q][2], b[q][3]);
                }
        }
        __syncthreads();            // all warps done reading K; reuse as e-tile

        float ss[4][2];
        #pragma unroll
        for (int nj = 0; nj < 4; nj++) { ss[nj][0] = 0.f; ss[nj][1] = 0.f; }

        #pragma unroll
        for (int ai = 0; ai < 2; ai++) {
            int r0 = wn * 32 + ai * 16 + gid;
            #pragma unroll
            for (int nj = 0; nj < 4; nj++) {
                float e0 = __expf(acc[ai][nj][0] * INV_SQRT);
                float e1 = __expf(acc[ai][nj][1] * INV_SQRT);
                float e2 = __expf(acc[ai][nj][2] * INV_SQRT);
                float e3 = __expf(acc[ai][nj][3] * INV_SQRT);
                __nv_bfloat162 h01, h23;
                h01.x = __float2bfloat16(e0); h01.y = __float2bfloat16(e1);
                h23.x = __float2bfloat16(e2); h23.y = __float2bfloat16(e3);
                int chn = wm * 4 + nj;       // m byte = (wm*32+nj*8+2tig)*2 = chn*16 + tig*4
                *(__nv_bfloat162*)(smK + SWZ8(r0, chn) + tig * 4)     = h01;
                *(__nv_bfloat162*)(smK + SWZ8(r0 + 8, chn) + tig * 4) = h23;
                ss[nj][0] += __bfloat162float(h01.x) + __bfloat162float(h23.x);
                ss[nj][1] += __bfloat162float(h01.y) + __bfloat162float(h23.y);
            }
        }

        // reduce over gid (lanes sharing tig): lane bits 2,3,4
        #pragma unroll
        for (int nj = 0; nj < 4; nj++) {
            #pragma unroll
            for (int off = 4; off < 32; off <<= 1) {
                ss[nj][0] += __shfl_xor_sync(0xffffffffu, ss[nj][0], off);
                ss[nj][1] += __shfl_xor_sync(0xffffffffu, ss[nj][1], off);
            }
        }
        if (lane < 4) {
            #pragma unroll
            for (int nj = 0; nj < 4; nj++) {
                red[wn * 64 + wm * 32 + nj * 8 + 2 * tig]     = ss[nj][0];
                red[wn * 64 + wm * 32 + nj * 8 + 2 * tig + 1] = ss[nj][1];
            }
        }
        __syncthreads();            // e-tile + red complete

        // coalesced Sb store: 64 rows x 64 m (128B per row)
        #pragma unroll
        for (int it = 0; it < 4; it++) {
            int row = (tid >> 3) + it * 16;
            int ch8 = tid & 7;
            *(uint4*)(Sp + (size_t)(n0 + row) * NDIM + m0 + ch8 * 8) =
                *(uint4*)(smK + SWZ8(row, ch8));
        }
        if (tid < 64)
            g_psum[((size_t)bl * NDIM + m0 + tid) * NTP + blockIdx.x] = red[tid] + red[64 + tid];

        __syncthreads();            // K/e buffer free before next cp.async
    }
}

// ---------------- kernel 3: alpha = 1/Z -------------------------------------
__global__ void stats_kernel()
{
    int idx = blockIdx.x * blockDim.x + threadIdx.x;
    if (idx >= BL * NDIM) return;
    const float* ps = g_psum + (size_t)idx * NTP;
    float Z = 0.f;
    #pragma unroll
    for (int t = 0; t < NTP; t++) Z += ps[t];
    g_alpha[idx] = 1.f / Z;
}

// ---------------- kernel 3b: fold alpha into Gt (in place) ------------------
__global__ void scale_kernel()
{
    size_t v = (size_t)blockIdx.x * blockDim.x + threadIdx.x;     // uint4 index
    const size_t nvec = (size_t)BL * CDIM * NDIM / 8;
    if (v >= nvec) return;
    size_t e0 = v * 8;
    size_t bl = e0 / ((size_t)CDIM * NDIM);
    size_t m  = e0 % NDIM;
    const float* al = g_alpha + bl * NDIM + m;
    uint4 u = *(uint4*)(g_Gt + e0);
    __nv_bfloat162* h = (__nv_bfloat162*)&u;
    #pragma unroll
    for (int j = 0; j < 4; j++) {
        float2 f = __bfloat1622float2(h[j]);
        h[j].x = __float2bfloat16(f.x * al[2 * j]);
        h[j].y = __float2bfloat16(f.y * al[2 * j + 1]);
    }
    *(uint4*)(g_Gt + e0) = u;
}

// ---------------- kernel 4: acc[c][n] = sum_m Gta[c][m] * e[n][m] ------------
#define KC 64
#define NC 32
#define STG_BYTES 32768
#define SMEM_ATT (3 * STG_BYTES)
__global__ __launch_bounds__(256, 2) void attnout_kernel()
{
    extern __shared__ char sm[];
    uint32_t sb = smem_u32(sm);

    int tid = threadIdx.x, lane = tid & 31, w = tid >> 5;
    int wc = w >> 2, wn = w & 3;
    int bl = blockIdx.y, n0 = blockIdx.x * 128;
    int mbase = blockIdx.z * 2048;

    const __nv_bfloat16* Gp = g_Gt + (size_t)bl * CDIM * NDIM;
    const __nv_bfloat16* Sp = g_Sb + (size_t)bl * NDIM * NDIM;

    int lrow = tid >> 3, lch = tid & 7;

    #pragma unroll
    for (int p = 0; p < 3; p++) {
        int mq = mbase + p * KC;
        uint32_t sA = sb + p * STG_BYTES, sB = sA + 16384;
        #pragma unroll
        for (int it = 0; it < 4; it++) {
            int row = lrow + it * 32;
            CP_ASYNC16(sA + SWZ8(row, lch), Gp + (size_t)row * NDIM + mq + lch * 8);
            CP_ASYNC16(sB + SWZ8(row, lch), Sp + (size_t)(n0 + row) * NDIM + mq + lch * 8);
        }
        CP_COMMIT();
    }

    float acc[4][4][4];
    #pragma unroll
    for (int i = 0; i < 4; i++)
        #pragma unroll
        for (int j = 0; j < 4; j++)
            #pragma unroll
            for (int q = 0; q < 4; q++) acc[i][j][q] = 0.f;

    int st = 0;
    for (int chk = 0; chk < NC; chk++) {
        CP_WAIT(2);
        __syncthreads();

        uint32_t sA = sb + st * STG_BYTES, sB = sA + 16384;
        #pragma unroll
        for (int ks = 0; ks < 4; ks++) {
            uint32_t a[4][4], b[2][4];
            #pragma unroll
            for (int mi = 0; mi < 4; mi++)
                ldmx4(a[mi], sA + SWZ8(wc * 64 + mi * 16 + (lane & 15), 2 * ks + (lane >> 4)));
            #pragma unroll
            for (int q = 0; q < 2; q++)
                ldmx4(b[q], sB + SWZ8(wn * 32 + q * 16 + (lane & 7) + ((lane >> 4) << 3),
                                      2 * ks + ((lane >> 3) & 1)));
            #pragma unroll
            for (int mi = 0; mi < 4; mi++)
                #pragma unroll
                for (int q = 0; q < 2; q++) {
                    mma16816(acc[mi][2 * q],     a[mi], b[q][0], b[q][1]);
                    mma16816(acc[mi][2 * q + 1], a[mi], b[q][2], b[q][3]);
                }
        }
        __syncthreads();

        if (chk + 3 < NC) {
            int mq = mbase + (chk + 3) * KC;
            #pragma unroll
            for (int it = 0; it < 4; it++) {
                int row = lrow + it * 32;
                CP_ASYNC16(sA + SWZ8(row, lch), Gp + (size_t)row * NDIM + mq + lch * 8);
                CP_ASYNC16(sB + SWZ8(row, lch), Sp + (size_t)(n0 + row) * NDIM + mq + lch * 8);
            }
        }
        CP_COMMIT();
        st = (st + 1 == 3) ? 0 : st + 1;
    }

    int gid = lane >> 2, tig = lane & 3;
    float* dstb = g_acc + ((size_t)(bl * 2 + blockIdx.z)) * CDIM * NDIM;
    #pragma unroll
    for (int mi = 0; mi < 4; mi++) {
        int c0 = wc * 64 + mi * 16 + gid;
        #pragma unroll
        for (int nj = 0; nj < 4; nj++) {
            int n = n0 + wn * 32 + nj * 8 + 2 * tig;
            *(float2*)(dstb + (size_t)c0 * NDIM + n)       = make_float2(acc[mi][nj][0], acc[mi][nj][1]);
            *(float2*)(dstb + (size_t)(c0 + 8) * NDIM + n) = make_float2(acc[mi][nj][2], acc[mi][nj][3]);
        }
    }
}

// ---------------- kernel 5: out = x + mean_l(acc) ---------------------------
__global__ void epilogue_kernel(const float* __restrict__ X, float* __restrict__ out)
{
    size_t idx = (size_t)blockIdx.x * blockDim.x + threadIdx.x;
    const size_t total = (size_t)BDIM * CDIM * NDIM;
    if (idx >= total) return;
    size_t b   = idx / ((size_t)CDIM * NDIM);
    size_t rem = idx % ((size_t)CDIM * NDIM);
    float s = 0.f;
    #pragma unroll
    for (int l = 0; l < LNUM; l++) {
        size_t base = ((size_t)(b * LNUM + l) * 2) * CDIM * NDIM;
        s += g_acc[base + rem] + g_acc[base + (size_t)CDIM * NDIM + rem];
    }
    out[idx] = X[idx] + s * (1.0f / LNUM);
}

// ---------------- launch -----------------------------------------------------
extern "C" void kernel_launch(void* const* d_in, const int* in_sizes, int n_in,
                              void* d_out, int out_size)
{
    const float* x  = (const float*)d_in[0];
    const float* W1 = (const float*)d_in[1];
    const float* b1 = (const float*)d_in[2];
    const float* W2 = (const float*)d_in[3];
    const float* b2 = (const float*)d_in[4];
    const float* Wg = (const float*)d_in[5];
    const float* bg = (const float*)d_in[6];
    float* out = (float*)d_out;

    cudaFuncSetAttribute(projmma_kernel, cudaFuncAttributeMaxDynamicSharedMemorySize, SMEM_PROJ);
    cudaFuncSetAttribute(score_kernel,   cudaFuncAttributeMaxDynamicSharedMemorySize, SMEM_SCORE);
    cudaFuncSetAttribute(attnout_kernel, cudaFuncAttributeMaxDynamicSharedMemorySize, SMEM_ATT);

    xt_kernel<<<dim3(NDIM / 32, CDIM / 32, BDIM), dim3(32, 8)>>>(x);
    wcvt_kernel<<<(3 * LNUM * CDIM * CDIM + 255) / 256, 256>>>(W1, W2, Wg);
    projmma_kernel<<<dim3(NT, 3, BL), 256, SMEM_PROJ>>>(b1, b2, bg);
    score_kernel<<<dim3(NTP, 8, BL), 128, SMEM_SCORE>>>();
    stats_kernel<<<(BL * NDIM + 255) / 256, 256>>>();
    scale_kernel<<<(unsigned)(((size_t)BL * CDIM * NDIM / 8 + 255) / 256), 256>>>();
    attnout_kernel<<<dim3(NT, BL, 2), 256, SMEM_ATT>>>();
    epilogue_kernel<<<(unsigned)(((size_t)BDIM * CDIM * NDIM + 255) / 256), 256>>>(x, out);
}

// round 11
// speedup vs baseline: 1.1156x; 1.0991x over previous
#include <cuda_runtime.h>
#include <cuda_bf16.h>
#include <cstdint>

#define BDIM 2
#define LNUM 6
#define CDIM 128
#define NDIM 4096
#define NT 32
#define NTILES 128                   // psum slots (n-tiles of 32 rows)
#define BL (BDIM*LNUM)
#define EXC (1.44269504088896f/64.0f)   // log2(e)/sqrt(4096)

// ---------------- scratch (static device memory; allocation-free) ----------
__device__ __nv_bfloat16 g_Xt[(size_t)BDIM*NDIM*CDIM];  // [b][n][c] bf16
__device__ __nv_bfloat16 g_Wb[(size_t)3*LNUM*CDIM*CDIM];// [p][l][o][c] bf16
__device__ __nv_bfloat16 g_Qb[(size_t)BL*NDIM*CDIM];    // [bl][n][c]
__device__ __nv_bfloat16 g_Kb[(size_t)BL*NDIM*CDIM];    // [bl][m][c]
__device__ __nv_bfloat16 g_Gt[(size_t)BL*CDIM*NDIM];    // [bl][c][m] (alpha folded by statscale)
__device__ uint32_t g_Sf[(size_t)BL*512*256*64];        // e fragments [bl][n8][m8p][lane][2]
__device__ float g_psum[(size_t)BL*NTILES*NDIM];        // [bl][tile32][m]
__device__ float g_acc[(size_t)BL*2*CDIM*NDIM];         // per-(layer,split) output [c][n]

// ---------------- helpers ----------------------------------------------------
__device__ __forceinline__ uint32_t smem_u32(const void* p) {
    uint32_t a;
    asm("{ .reg .u64 t; cvta.to.shared.u64 t, %1; cvt.u32.u64 %0, t; }" : "=r"(a) : "l"(p));
    return a;
}

// swizzled byte offset inside [rows][256B] tile: chunk = 16B unit (0..15)
__device__ __forceinline__ uint32_t SWZ(int row, int chunk) {
    return (uint32_t)row * 256u + (uint32_t)((chunk ^ (row & 7)) << 4);
}
// swizzled byte offset inside [rows][128B] tile: chunk = 16B unit (0..7)
__device__ __forceinline__ uint32_t SWZ8(int row, int chunk) {
    return (uint32_t)row * 128u + (uint32_t)((chunk ^ (row & 7)) << 4);
}

__device__ __forceinline__ void ldmx4(uint32_t* r, uint32_t addr) {
    asm volatile("ldmatrix.sync.aligned.m8n8.x4.shared.b16 {%0,%1,%2,%3}, [%4];"
        : "=r"(r[0]), "=r"(r[1]), "=r"(r[2]), "=r"(r[3]) : "r"(addr));
}

__device__ __forceinline__ void lds64(uint32_t& x, uint32_t& y, uint32_t addr) {
    asm volatile("ld.shared.v2.u32 {%0,%1}, [%2];" : "=r"(x), "=r"(y) : "r"(addr));
}

__device__ __forceinline__ void mma16816(float* d, const uint32_t* a, uint32_t b0, uint32_t b1) {
    asm volatile("mma.sync.aligned.m16n8k16.row.col.f32.bf16.bf16.f32 "
        "{%0,%1,%2,%3}, {%4,%5,%6,%7}, {%8,%9}, {%0,%1,%2,%3};"
        : "+f"(d[0]), "+f"(d[1]), "+f"(d[2]), "+f"(d[3])
        : "r"(a[0]), "r"(a[1]), "r"(a[2]), "r"(a[3]), "r"(b0), "r"(b1));
}

__device__ __forceinline__ float ex2f(float x) {
    float y; asm("ex2.approx.f32 %0, %1;" : "=f"(y) : "f"(x)); return y;
}
__device__ __forceinline__ uint32_t packbf(float a, float b) {
    __nv_bfloat162 h = __floats2bfloat162_rn(a, b);
    return *(uint32_t*)&h;
}

#define CP_ASYNC16(dst, src) \
    asm volatile("cp.async.cg.shared.global [%0], [%1], 16;" :: "r"(dst), "l"(src))
#define CP_COMMIT() asm volatile("cp.async.commit_group;" ::: "memory")
#define CP_WAIT(n)  asm volatile("cp.async.wait_group %0;" :: "n"(n) : "memory")

// ---------------- kernel 0a: X -> Xt bf16 (transpose) -----------------------
__global__ void xt_kernel(const float* __restrict__ X)
{
    __shared__ float t[32][33];
    int b = blockIdx.z, c0 = blockIdx.y * 32, n0 = blockIdx.x * 32;
    int tx = threadIdx.x, ty = threadIdx.y;   // 32 x 8
    const float* Xb = X + (size_t)b * CDIM * NDIM;
    #pragma unroll
    for (int i = 0; i < 4; i++)
        t[ty + 8 * i][tx] = Xb[(size_t)(c0 + ty + 8 * i) * NDIM + n0 + tx];
    __syncthreads();
    __nv_bfloat16* dst = g_Xt + (size_t)b * NDIM * CDIM;
    #pragma unroll
    for (int i = 0; i < 4; i++)
        dst[(size_t)(n0 + ty + 8 * i) * CDIM + c0 + tx] = __float2bfloat16(t[tx][ty + 8 * i]);
}

// ---------------- kernel 0b: weights -> bf16 --------------------------------
__global__ void wcvt_kernel(const float* __restrict__ W1, const float* __restrict__ W2,
                            const float* __restrict__ Wg)
{
    int idx = blockIdx.x * blockDim.x + threadIdx.x;
    const int per = LNUM * CDIM * CDIM;
    if (idx >= 3 * per) return;
    const float* src = (idx < per) ? W1 : (idx < 2 * per) ? W2 : Wg;
    g_Wb[idx] = __float2bfloat16(src[idx % per]);
}

// ---------------- kernel 1: projections via mma.sync ------------------------
#define SMEM_PROJ 65536
__global__ __launch_bounds__(256) void projmma_kernel(const float* __restrict__ b1,
                                                      const float* __restrict__ b2,
                                                      const float* __restrict__ bg)
{
    extern __shared__ char sm[];
    uint32_t sbA = smem_u32(sm);
    uint32_t sbB = sbA + 32768;

    int tid = threadIdx.x, lane = tid & 31, w = tid >> 5;
    int wn = w >> 2, wm = w & 3;                 // 2(row) x 4(col) warp grid
    int bl = blockIdx.z, p = blockIdx.y, n0 = blockIdx.x * 128;
    int b = bl / LNUM, l = bl % LNUM;

    const __nv_bfloat16* Xp = g_Xt + ((size_t)b * NDIM + n0) * CDIM;
    const __nv_bfloat16* Wp = g_Wb + (size_t)(p * LNUM + l) * CDIM * CDIM;
    const float* bias = ((p == 0) ? b1 : (p == 1) ? b2 : bg) + l * CDIM;

    const __nv_bfloat16* Ap = (p < 2) ? Xp : Wp;
    const __nv_bfloat16* Bp = (p < 2) ? Wp : Xp;

    #pragma unroll
    for (int it = 0; it < 8; it++) {
        int s = tid + it * 256;
        int row = s >> 4, ch = s & 15;
        CP_ASYNC16(sbA + SWZ(row, ch), Ap + (size_t)row * CDIM + ch * 8);
        CP_ASYNC16(sbB + SWZ(row, ch), Bp + (size_t)row * CDIM + ch * 8);
    }
    CP_COMMIT();
    CP_WAIT(0);
    __syncthreads();

    float acc[4][4][4];
    #pragma unroll
    for (int i = 0; i < 4; i++)
        #pragma unroll
        for (int j = 0; j < 4; j++)
            #pragma unroll
            for (int q = 0; q < 4; q++) acc[i][j][q] = 0.f;

    #pragma unroll
    for (int ks = 0; ks < 8; ks++) {
        uint32_t a[4][4], bfrag[2][4];
        #pragma unroll
        for (int mi = 0; mi < 4; mi++)
            ldmx4(a[mi], sbA + SWZ(wn * 64 + mi * 16 + (lane & 15), 2 * ks + (lane >> 4)));
        #pragma unroll
        for (int q = 0; q < 2; q++)
            ldmx4(bfrag[q], sbB + SWZ(wm * 32 + q * 16 + (lane & 7) + ((lane >> 4) << 3),
                                      2 * ks + ((lane >> 3) & 1)));
        #pragma unroll
        for (int mi = 0; mi < 4; mi++)
            #pragma unroll
            for (int q = 0; q < 2; q++) {
                mma16816(acc[mi][2 * q],     a[mi], bfrag[q][0], bfrag[q][1]);
                mma16816(acc[mi][2 * q + 1], a[mi], bfrag[q][2], bfrag[q][3]);
            }
    }

    int gid = lane >> 2, tig = lane & 3;
    __syncthreads();   // all warps done reading operand smem; reuse sbA as out-tile

    #pragma unroll
    for (int mi = 0; mi < 4; mi++) {
        int r0 = wn * 64 + mi * 16 + gid;
        float brow0 = 0.f, brow8 = 0.f;
        if (p == 2) { brow0 = bias[r0]; brow8 = bias[r0 + 8]; }
        #pragma unroll
        for (int nj = 0; nj < 4; nj++) {
            int mc = wm * 32 + nj * 8 + 2 * tig;
            float v0 = acc[mi][nj][0], v1 = acc[mi][nj][1];
            float v2 = acc[mi][nj][2], v3 = acc[mi][nj][3];
            if (p < 2) {
                float bc0 = bias[mc], bc1 = bias[mc + 1];
                v0 += bc0; v1 += bc1; v2 += bc0; v3 += bc1;
            } else {
                v0 += brow0; v1 += brow0; v2 += brow8; v3 += brow8;
            }
            __nv_bfloat162 h01, h23;
            h01.x = __float2bfloat16(v0); h01.y = __float2bfloat16(v1);
            h23.x = __float2bfloat16(v2); h23.y = __float2bfloat16(v3);
            int chn = wm * 4 + nj;
            *(__nv_bfloat162*)(sm + SWZ(r0, chn) + tig * 4)     = h01;
            *(__nv_bfloat162*)(sm + SWZ(r0 + 8, chn) + tig * 4) = h23;
        }
    }
    __syncthreads();

    if (p < 2) {
        __nv_bfloat16* dst = (p == 0 ? g_Qb : g_Kb) + ((size_t)bl * NDIM + n0) * CDIM;
        #pragma unroll
        for (int it = 0; it < 8; it++) {
            int s = tid + it * 256;
            int row = s >> 4, ch = s & 15;
            *(uint4*)(dst + (size_t)row * CDIM + ch * 8) = *(uint4*)(sm + SWZ(row, ch));
        }
    } else {
        __nv_bfloat16* dst = g_Gt + (size_t)bl * CDIM * NDIM;
        #pragma unroll
        for (int it = 0; it < 8; it++) {
            int s = tid + it * 256;
            int row = s >> 4, ch = s & 15;
            *(uint4*)(dst + (size_t)row * NDIM + n0 + ch * 8) = *(uint4*)(sm + SWZ(row, ch));
        }
    }
}

// ---------------- kernel 2: scores v6 — fragment-direct Sb ------------------
// CTA tile 64n x 64m; warp grid 2(n) x 2(m), warp tile 32x32.
// Q resident (16KB); loops 8 m-tiles of 64. Epilogue: regs -> gmem only
// (no smem staging). smem 32KB -> 6 CTA/SM.
#define SMEM_SCORE 32768
__global__ __launch_bounds__(128, 6) void score_kernel()
{
    extern __shared__ char sm[];
    uint32_t sbQ = smem_u32(sm);
    uint32_t sbK = sbQ + 16384;

    int tid = threadIdx.x, lane = tid & 31, w = tid >> 5;
    int wn = w >> 1, wm = w & 1;                 // 2(n) x 2(m) warp grid
    int bl = blockIdx.z, n0 = blockIdx.x * 64, mg = blockIdx.y * 512;

    const __nv_bfloat16* Qp = g_Qb + (size_t)bl * NDIM * CDIM;
    const __nv_bfloat16* Kp = g_Kb + (size_t)bl * NDIM * CDIM;

    int lrow = tid >> 4, lch = tid & 15;         // loader: 8 rows x 16 chunks per it

    // Q tile (64 rows x 256B), loaded once
    #pragma unroll
    for (int it = 0; it < 8; it++) {
        int row = lrow + it * 8;
        CP_ASYNC16(sbQ + SWZ(row, lch), Qp + (size_t)(n0 + row) * CDIM + lch * 8);
    }
    CP_COMMIT();
    // K tile 0
    #pragma unroll
    for (int it = 0; it < 8; it++) {
        int row = lrow + it * 8;
        CP_ASYNC16(sbK + SWZ(row, lch), Kp + (size_t)(mg + row) * CDIM + lch * 8);
    }
    CP_COMMIT();

    int gid = lane >> 2, tig = lane & 3;
    int slot = blockIdx.x * 2 + wn;              // psum tile (32 n rows)

    for (int mi = 0; mi < 8; mi++) {
        CP_WAIT(0);
        __syncthreads();

        float acc[2][4][4];
        #pragma unroll
        for (int i = 0; i < 2; i++)
            #pragma unroll
            for (int j = 0; j < 4; j++)
                #pragma unroll
                for (int q = 0; q < 4; q++) acc[i][j][q] = 0.f;

        #pragma unroll
        for (int ks = 0; ks < 8; ks++) {
            uint32_t a[2][4], b[2][4];
            #pragma unroll
            for (int ai = 0; ai < 2; ai++)
                ldmx4(a[ai], sbQ + SWZ(wn * 32 + ai * 16 + (lane & 15), 2 * ks + (lane >> 4)));
            #pragma unroll
            for (int q = 0; q < 2; q++)
                ldmx4(b[q], sbK + SWZ(wm * 32 + q * 16 + (lane & 7) + ((lane >> 4) << 3),
                                      2 * ks + ((lane >> 3) & 1)));
            #pragma unroll
            for (int ai = 0; ai < 2; ai++)
                #pragma unroll
                for (int q = 0; q < 2; q++) {
                    mma16816(acc[ai][2 * q],     a[ai], b[q][0], b[q][1]);
                    mma16816(acc[ai][2 * q + 1], a[ai], b[q][2], b[q][3]);
                }
        }
        __syncthreads();            // all warps done reading K

        // prefetch next K (overlaps the epilogue below)
        if (mi + 1 < 8) {
            int mn = mg + (mi + 1) * 64;
            #pragma unroll
            for (int it = 0; it < 8; it++) {
                int row = lrow + it * 8;
                CP_ASYNC16(sbK + SWZ(row, lch), Kp + (size_t)(mn + row) * CDIM + lch * 8);
            }
        }
        CP_COMMIT();

        // epilogue: exp -> bf16x2 fragment units -> coalesced STG.64
        int m0 = mg + mi * 64;
        int m8pb = (m0 >> 4) + wm * 2;           // m8-pair base for this warp
        float ss0[4], ss1[4];
        #pragma unroll
        for (int nj = 0; nj < 4; nj++) { ss0[nj] = 0.f; ss1[nj] = 0.f; }

        #pragma unroll
        for (int ai = 0; ai < 2; ai++) {
            size_t n8 = (size_t)(n0 >> 3) + wn * 4 + ai * 2;
            #pragma unroll
            for (int njp = 0; njp < 2; njp++) {
                float e0[4], e1[4];              // e0 = nj even, e1 = nj odd
                #pragma unroll
                for (int q = 0; q < 4; q++) {
                    e0[q] = ex2f(acc[ai][2 * njp][q] * EXC);
                    e1[q] = ex2f(acc[ai][2 * njp + 1][q] * EXC);
                }
                ss0[2 * njp]     += e0[0] + e0[2];
                ss1[2 * njp]     += e0[1] + e0[3];
                ss0[2 * njp + 1] += e1[0] + e1[2];
                ss1[2 * njp + 1] += e1[1] + e1[3];
                uint2 v0, v1;
                v0.x = packbf(e0[0], e0[1]); v0.y = packbf(e1[0], e1[1]);   // rows gid
                v1.x = packbf(e0[2], e0[3]); v1.y = packbf(e1[2], e1[3]);   // rows gid+8
                size_t i0 = ((((size_t)bl * 512 + n8) * 256) + m8pb + njp) * 64 + lane * 2;
                *(uint2*)&g_Sf[i0] = v0;
                *(uint2*)&g_Sf[i0 + 256 * 64] = v1;                          // n8+1
            }
        }

        // reduce over gid lanes (share tig)
        #pragma unroll
        for (int nj = 0; nj < 4; nj++) {
            #pragma unroll
            for (int off = 4; off < 32; off <<= 1) {
                ss0[nj] += __shfl_xor_sync(0xffffffffu, ss0[nj], off);
                ss1[nj] += __shfl_xor_sync(0xffffffffu, ss1[nj], off);
            }
        }
        if (lane < 4) {
            float* pp = g_psum + ((size_t)bl * NTILES + slot) * NDIM + m0 + wm * 32;
            #pragma unroll
            for (int nj = 0; nj < 4; nj++) {
                pp[nj * 8 + 2 * tig]     = ss0[nj];
                pp[nj * 8 + 2 * tig + 1] = ss1[nj];
            }
        }
    }
}

// ---------------- kernel 3: alpha = 1/Z, fold into Gt ------------------------
__global__ void statscale_kernel()
{
    int bl = blockIdx.y;
    int m = blockIdx.x * 128 + threadIdx.x;
    const float* ps = g_psum + (size_t)bl * NTILES * NDIM + m;
    float Z = 0.f;
    #pragma unroll 8
    for (int t = 0; t < NTILES; t++) Z += ps[(size_t)t * NDIM];
    float al = 1.f / Z;
    __nv_bfloat16* G = g_Gt + (size_t)bl * CDIM * NDIM + m;
    #pragma unroll 4
    for (int c = 0; c < CDIM; c++) {
        float v = __bfloat162float(G[(size_t)c * NDIM]);
        G[(size_t)c * NDIM] = __float2bfloat16(v * al);
    }
}

// ---------------- kernel 4: acc[c][n] = sum_m Gta[c][m] * e[n][m] ------------
// B read directly as fragment units (LDS.64), A via ldmatrix.
#define KC 64
#define NC 32
#define STG_BYTES 32768
#define SMEM_ATT (3 * STG_BYTES)
__global__ __launch_bounds__(256, 2) void attnout_kernel()
{
    extern __shared__ char sm[];
    uint32_t sb = smem_u32(sm);

    int tid = threadIdx.x, lane = tid & 31, w = tid >> 5;
    int wc = w >> 2, wn = w & 3;                 // 2(c) x 4(n) warp grid
    int bl = blockIdx.y, n0 = blockIdx.x * 128;
    int mbase = blockIdx.z * 2048;
    int n08 = n0 >> 3;

    const __nv_bfloat16* Gp = g_Gt + (size_t)bl * CDIM * NDIM;

    int lrow = tid >> 3, lch = tid & 7;

    #pragma unroll
    for (int p = 0; p < 3; p++) {
        int mq = mbase + p * KC;
        uint32_t sA = sb + p * STG_BYTES, sB = sA + 16384;
        #pragma unroll
        for (int it = 0; it < 4; it++) {
            int row = lrow + it * 32;
            CP_ASYNC16(sA + SWZ8(row, lch), Gp + (size_t)row * NDIM + mq + lch * 8);
        }
        int mq16 = mq >> 4;
        #pragma unroll
        for (int it = 0; it < 4; it++) {
            int tp = tid + it * 256;
            int n8l = tp >> 6, inner = tp & 63;
            const uint32_t* src = g_Sf + (((size_t)bl * 512 + n08 + n8l) * 256 + mq16) * 64 + inner * 4;
            CP_ASYNC16(sB + tp * 16, src);
        }
        CP_COMMIT();
    }

    float acc[4][4][4];
    #pragma unroll
    for (int i = 0; i < 4; i++)
        #pragma unroll
        for (int j = 0; j < 4; j++)
            #pragma unroll
            for (int q = 0; q < 4; q++) acc[i][j][q] = 0.f;

    int st = 0;
    for (int chk = 0; chk < NC; chk++) {
        CP_WAIT(2);
        __syncthreads();

        uint32_t sA = sb + st * STG_BYTES, sB = sA + 16384;
        #pragma unroll
        for (int ks = 0; ks < 4; ks++) {
            uint32_t a[4][4], b0[4], b1[4];
            #pragma unroll
            for (int mi = 0; mi < 4; mi++)
                ldmx4(a[mi], sA + SWZ8(wc * 64 + mi * 16 + (lane & 15), 2 * ks + (lane >> 4)));
            #pragma unroll
            for (int u = 0; u < 4; u++)
                lds64(b0[u], b1[u], sB + ((((wn * 4 + u) * 4 + ks) * 32 + lane) << 3));
            #pragma unroll
            for (int mi = 0; mi < 4; mi++)
                #pragma unroll
                for (int u = 0; u < 4; u++)
                    mma16816(acc[mi][u], a[mi], b0[u], b1[u]);
        }
        __syncthreads();

        if (chk + 3 < NC) {
            int mq = mbase + (chk + 3) * KC;
            #pragma unroll
            for (int it = 0; it < 4; it++) {
                int row = lrow + it * 32;
                CP_ASYNC16(sA + SWZ8(row, lch), Gp + (size_t)row * NDIM + mq + lch * 8);
            }
            int mq16 = mq >> 4;
            #pragma unroll
            for (int it = 0; it < 4; it++) {
                int tp = tid + it * 256;
                int n8l = tp >> 6, inner = tp & 63;
                const uint32_t* src = g_Sf + (((size_t)bl * 512 + n08 + n8l) * 256 + mq16) * 64 + inner * 4;
                CP_ASYNC16(sB + tp * 16, src);
            }
        }
        CP_COMMIT();
        st = (st + 1 == 3) ? 0 : st + 1;
    }

    int gid = lane >> 2, tig = lane & 3;
    float* dstb = g_acc + ((size_t)(bl * 2 + blockIdx.z)) * CDIM * NDIM;
    #pragma unroll
    for (int mi = 0; mi < 4; mi++) {
        int c0 = wc * 64 + mi * 16 + gid;
        #pragma unroll
        for (int nj = 0; nj < 4; nj++) {
            int n = n0 + wn * 32 + nj * 8 + 2 * tig;
            *(float2*)(dstb + (size_t)c0 * NDIM + n)       = make_float2(acc[mi][nj][0], acc[mi][nj][1]);
            *(float2*)(dstb + (size_t)(c0 + 8) * NDIM + n) = make_float2(acc[mi][nj][2], acc[mi][nj][3]);
        }
    }
}

// ---------------- kernel 5: out = x + mean_l(acc) ---------------------------
__global__ void epilogue_kernel(const float* __restrict__ X, float* __restrict__ out)
{
    size_t idx = (size_t)blockIdx.x * blockDim.x + threadIdx.x;
    const size_t total = (size_t)BDIM * CDIM * NDIM;
    if (idx >= total) return;
    size_t b   = idx / ((size_t)CDIM * NDIM);
    size_t rem = idx % ((size_t)CDIM * NDIM);
    float s = 0.f;
    #pragma unroll
    for (int l = 0; l < LNUM; l++) {
        size_t base = ((size_t)(b * LNUM + l) * 2) * CDIM * NDIM;
        s += g_acc[base + rem] + g_acc[base + (size_t)CDIM * NDIM + rem];
    }
    out[idx] = X[idx] + s * (1.0f / LNUM);
}

// ---------------- launch -----------------------------------------------------
extern "C" void kernel_launch(void* const* d_in, const int* in_sizes, int n_in,
                              void* d_out, int out_size)
{
    const float* x  = (const float*)d_in[0];
    const float* W1 = (const float*)d_in[1];
    const float* b1 = (const float*)d_in[2];
    const float* W2 = (const float*)d_in[3];
    const float* b2 = (const float*)d_in[4];
    const float* Wg = (const float*)d_in[5];
    const float* bg = (const float*)d_in[6];
    float* out = (float*)d_out;

    cudaFuncSetAttribute(projmma_kernel, cudaFuncAttributeMaxDynamicSharedMemorySize, SMEM_PROJ);
    cudaFuncSetAttribute(score_kernel,   cudaFuncAttributeMaxDynamicSharedMemorySize, SMEM_SCORE);
    cudaFuncSetAttribute(attnout_kernel, cudaFuncAttributeMaxDynamicSharedMemorySize, SMEM_ATT);

    xt_kernel<<<dim3(NDIM / 32, CDIM / 32, BDIM), dim3(32, 8)>>>(x);
    wcvt_kernel<<<(3 * LNUM * CDIM * CDIM + 255) / 256, 256>>>(W1, W2, Wg);
    projmma_kernel<<<dim3(NT, 3, BL), 256, SMEM_PROJ>>>(b1, b2, bg);
    score_kernel<<<dim3(64, 8, BL), 128, SMEM_SCORE>>>();
    statscale_kernel<<<dim3(NDIM / 128, BL), 128>>>();
    attnout_kernel<<<dim3(NT, BL, 2), 256, SMEM_ATT>>>();
    epilogue_kernel<<<(unsigned)(((size_t)BDIM * CDIM * NDIM + 255) / 256), 256>>>(x, out);
}

// round 12
// speedup vs baseline: 1.1157x; 1.0002x over previous
#include <cuda_runtime.h>
#include <cuda_bf16.h>
#include <cstdint>

#define BDIM 2
#define LNUM 6
#define CDIM 128
#define NDIM 4096
#define NT 32
#define NTILES 128                   // psum slots (n-tiles of 32 rows)
#define BL (BDIM*LNUM)
#define EXC (1.44269504088896f/64.0f)   // log2(e)/sqrt(4096)

// ---------------- scratch (static device memory; allocation-free) ----------
__device__ __nv_bfloat16 g_Xt[(size_t)BDIM*NDIM*CDIM];  // [b][n][c] bf16
__device__ __nv_bfloat16 g_Wb[(size_t)3*LNUM*CDIM*CDIM];// [p][l][o][c] bf16
__device__ __nv_bfloat16 g_Qb[(size_t)BL*NDIM*CDIM];    // [bl][n][c]
__device__ __nv_bfloat16 g_Kb[(size_t)BL*NDIM*CDIM];    // [bl][m][c]
__device__ __nv_bfloat16 g_Gt[(size_t)BL*CDIM*NDIM];    // [bl][c][m] (alpha folded by statscale)
__device__ uint32_t g_Sf[(size_t)BL*512*256*64];        // e fragments [bl][n8][m8p][lane][2]
__device__ float g_psum[(size_t)BL*NTILES*NDIM];        // [bl][tile32][m]
__device__ float g_acc[(size_t)BL*2*CDIM*NDIM];         // per-(layer,split) output [c][n]

// ---------------- helpers ----------------------------------------------------
__device__ __forceinline__ uint32_t smem_u32(const void* p) {
    uint32_t a;
    asm("{ .reg .u64 t; cvta.to.shared.u64 t, %1; cvt.u32.u64 %0, t; }" : "=r"(a) : "l"(p));
    return a;
}

// swizzled byte offset inside [rows][256B] tile: chunk = 16B unit (0..15)
__device__ __forceinline__ uint32_t SWZ(int row, int chunk) {
    return (uint32_t)row * 256u + (uint32_t)((chunk ^ (row & 7)) << 4);
}
// swizzled byte offset inside [rows][128B] tile: chunk = 16B unit (0..7)
__device__ __forceinline__ uint32_t SWZ8(int row, int chunk) {
    return (uint32_t)row * 128u + (uint32_t)((chunk ^ (row & 7)) << 4);
}

__device__ __forceinline__ void ldmx4(uint32_t* r, uint32_t addr) {
    asm volatile("ldmatrix.sync.aligned.m8n8.x4.shared.b16 {%0,%1,%2,%3}, [%4];"
        : "=r"(r[0]), "=r"(r[1]), "=r"(r[2]), "=r"(r[3]) : "r"(addr));
}

__device__ __forceinline__ void lds64(uint32_t& x, uint32_t& y, uint32_t addr) {
    asm volatile("ld.shared.v2.u32 {%0,%1}, [%2];" : "=r"(x), "=r"(y) : "r"(addr));
}

__device__ __forceinline__ void mma16816(float* d, const uint32_t* a, uint32_t b0, uint32_t b1) {
    asm volatile("mma.sync.aligned.m16n8k16.row.col.f32.bf16.bf16.f32 "
        "{%0,%1,%2,%3}, {%4,%5,%6,%7}, {%8,%9}, {%0,%1,%2,%3};"
        : "+f"(d[0]), "+f"(d[1]), "+f"(d[2]), "+f"(d[3])
        : "r"(a[0]), "r"(a[1]), "r"(a[2]), "r"(a[3]), "r"(b0), "r"(b1));
}

__device__ __forceinline__ float ex2f(float x) {
    float y; asm("ex2.approx.f32 %0, %1;" : "=f"(y) : "f"(x)); return y;
}
__device__ __forceinline__ uint32_t packbf(float a, float b) {
    __nv_bfloat162 h = __floats2bfloat162_rn(a, b);
    return *(uint32_t*)&h;
}

#define CP_ASYNC16(dst, src) \
    asm volatile("cp.async.cg.shared.global [%0], [%1], 16;" :: "r"(dst), "l"(src))
#define CP_COMMIT() asm volatile("cp.async.commit_group;" ::: "memory")
#define CP_WAIT(n)  asm volatile("cp.async.wait_group %0;" :: "n"(n) : "memory")

// ---------------- kernel 0a: X -> Xt bf16 (transpose) -----------------------
__global__ void xt_kernel(const float* __restrict__ X)
{
    __shared__ float t[32][33];
    int b = blockIdx.z, c0 = blockIdx.y * 32, n0 = blockIdx.x * 32;
    int tx = threadIdx.x, ty = threadIdx.y;   // 32 x 8
    const float* Xb = X + (size_t)b * CDIM * NDIM;
    #pragma unroll
    for (int i = 0; i < 4; i++)
        t[ty + 8 * i][tx] = Xb[(size_t)(c0 + ty + 8 * i) * NDIM + n0 + tx];
    __syncthreads();
    __nv_bfloat16* dst = g_Xt + (size_t)b * NDIM * CDIM;
    #pragma unroll
    for (int i = 0; i < 4; i++)
        dst[(size_t)(n0 + ty + 8 * i) * CDIM + c0 + tx] = __float2bfloat16(t[tx][ty + 8 * i]);
}

// ---------------- kernel 0b: weights -> bf16 --------------------------------
__global__ void wcvt_kernel(const float* __restrict__ W1, const float* __restrict__ W2,
                            const float* __restrict__ Wg)
{
    int idx = blockIdx.x * blockDim.x + threadIdx.x;
    const int per = LNUM * CDIM * CDIM;
    if (idx >= 3 * per) return;
    const float* src = (idx < per) ? W1 : (idx < 2 * per) ? W2 : Wg;
    g_Wb[idx] = __float2bfloat16(src[idx % per]);
}

// ---------------- kernel 1: projections via mma.sync ------------------------
#define SMEM_PROJ 65536
__global__ __launch_bounds__(256) void projmma_kernel(const float* __restrict__ b1,
                                                      const float* __restrict__ b2,
                                                      const float* __restrict__ bg)
{
    extern __shared__ char sm[];
    uint32_t sbA = smem_u32(sm);
    uint32_t sbB = sbA + 32768;

    int tid = threadIdx.x, lane = tid & 31, w = tid >> 5;
    int wn = w >> 2, wm = w & 3;                 // 2(row) x 4(col) warp grid
    int bl = blockIdx.z, p = blockIdx.y, n0 = blockIdx.x * 128;
    int b = bl / LNUM, l = bl % LNUM;

    const __nv_bfloat16* Xp = g_Xt + ((size_t)b * NDIM + n0) * CDIM;
    const __nv_bfloat16* Wp = g_Wb + (size_t)(p * LNUM + l) * CDIM * CDIM;
    const float* bias = ((p == 0) ? b1 : (p == 1) ? b2 : bg) + l * CDIM;

    const __nv_bfloat16* Ap = (p < 2) ? Xp : Wp;
    const __nv_bfloat16* Bp = (p < 2) ? Wp : Xp;

    #pragma unroll
    for (int it = 0; it < 8; it++) {
        int s = tid + it * 256;
        int row = s >> 4, ch = s & 15;
        CP_ASYNC16(sbA + SWZ(row, ch), Ap + (size_t)row * CDIM + ch * 8);
        CP_ASYNC16(sbB + SWZ(row, ch), Bp + (size_t)row * CDIM + ch * 8);
    }
    CP_COMMIT();
    CP_WAIT(0);
    __syncthreads();

    float acc[4][4][4];
    #pragma unroll
    for (int i = 0; i < 4; i++)
        #pragma unroll
        for (int j = 0; j < 4; j++)
            #pragma unroll
            for (int q = 0; q < 4; q++) acc[i][j][q] = 0.f;

    #pragma unroll
    for (int ks = 0; ks < 8; ks++) {
        uint32_t a[4][4], bfrag[2][4];
        #pragma unroll
        for (int mi = 0; mi < 4; mi++)
            ldmx4(a[mi], sbA + SWZ(wn * 64 + mi * 16 + (lane & 15), 2 * ks + (lane >> 4)));
        #pragma unroll
        for (int q = 0; q < 2; q++)
            ldmx4(bfrag[q], sbB + SWZ(wm * 32 + q * 16 + (lane & 7) + ((lane >> 4) << 3),
                                      2 * ks + ((lane >> 3) & 1)));
        #pragma unroll
        for (int mi = 0; mi < 4; mi++)
            #pragma unroll
            for (int q = 0; q < 2; q++) {
                mma16816(acc[mi][2 * q],     a[mi], bfrag[q][0], bfrag[q][1]);
                mma16816(acc[mi][2 * q + 1], a[mi], bfrag[q][2], bfrag[q][3]);
            }
    }

    int gid = lane >> 2, tig = lane & 3;
    __syncthreads();   // all warps done reading operand smem; reuse sbA as out-tile

    #pragma unroll
    for (int mi = 0; mi < 4; mi++) {
        int r0 = wn * 64 + mi * 16 + gid;
        float brow0 = 0.f, brow8 = 0.f;
        if (p == 2) { brow0 = bias[r0]; brow8 = bias[r0 + 8]; }
        #pragma unroll
        for (int nj = 0; nj < 4; nj++) {
            int mc = wm * 32 + nj * 8 + 2 * tig;
            float v0 = acc[mi][nj][0], v1 = acc[mi][nj][1];
            float v2 = acc[mi][nj][2], v3 = acc[mi][nj][3];
            if (p < 2) {
                float bc0 = bias[mc], bc1 = bias[mc + 1];
                v0 += bc0; v1 += bc1; v2 += bc0; v3 += bc1;
            } else {
                v0 += brow0; v1 += brow0; v2 += brow8; v3 += brow8;
            }
            __nv_bfloat162 h01, h23;
            h01.x = __float2bfloat16(v0); h01.y = __float2bfloat16(v1);
            h23.x = __float2bfloat16(v2); h23.y = __float2bfloat16(v3);
            int chn = wm * 4 + nj;
            *(__nv_bfloat162*)(sm + SWZ(r0, chn) + tig * 4)     = h01;
            *(__nv_bfloat162*)(sm + SWZ(r0 + 8, chn) + tig * 4) = h23;
        }
    }
    __syncthreads();

    if (p < 2) {
        __nv_bfloat16* dst = (p == 0 ? g_Qb : g_Kb) + ((size_t)bl * NDIM + n0) * CDIM;
        #pragma unroll
        for (int it = 0; it < 8; it++) {
            int s = tid + it * 256;
            int row = s >> 4, ch = s & 15;
            *(uint4*)(dst + (size_t)row * CDIM + ch * 8) = *(uint4*)(sm + SWZ(row, ch));
        }
    } else {
        __nv_bfloat16* dst = g_Gt + (size_t)bl * CDIM * NDIM;
        #pragma unroll
        for (int it = 0; it < 8; it++) {
            int s = tid + it * 256;
            int row = s >> 4, ch = s & 15;
            *(uint4*)(dst + (size_t)row * NDIM + n0 + ch * 8) = *(uint4*)(sm + SWZ(row, ch));
        }
    }
}

// ---------------- kernel 2: scores v7 — 32x64 warp tiles, frag-direct Sb ----
// CTA tile 64n x 128m; warp grid 2(n) x 2(m), warp tile 32x64 (acc 64 regs).
// Q resident (16KB); loops 8 m-tiles of 128; K buffer 32KB. 4 CTA/SM.
#define SMEM_SCORE 49152
__global__ __launch_bounds__(128, 4) void score_kernel()
{
    extern __shared__ char sm[];
    uint32_t sbQ = smem_u32(sm);
    uint32_t sbK = sbQ + 16384;

    int tid = threadIdx.x, lane = tid & 31, w = tid >> 5;
    int wn = w >> 1, wm = w & 1;                 // 2(n) x 2(m) warp grid
    int bl = blockIdx.z, n0 = blockIdx.x * 64, mg = blockIdx.y * 1024;

    const __nv_bfloat16* Qp = g_Qb + (size_t)bl * NDIM * CDIM;
    const __nv_bfloat16* Kp = g_Kb + (size_t)bl * NDIM * CDIM;

    int lrow = tid >> 4, lch = tid & 15;         // loader: 8 rows x 16 chunks per it

    // Q tile (64 rows x 256B), loaded once
    #pragma unroll
    for (int it = 0; it < 8; it++) {
        int row = lrow + it * 8;
        CP_ASYNC16(sbQ + SWZ(row, lch), Qp + (size_t)(n0 + row) * CDIM + lch * 8);
    }
    CP_COMMIT();
    // K tile 0 (128 rows x 256B)
    #pragma unroll
    for (int it = 0; it < 16; it++) {
        int row = lrow + it * 8;
        CP_ASYNC16(sbK + SWZ(row, lch), Kp + (size_t)(mg + row) * CDIM + lch * 8);
    }
    CP_COMMIT();

    int gid = lane >> 2, tig = lane & 3;
    int slot = blockIdx.x * 2 + wn;              // psum tile (32 n rows)

    for (int mi = 0; mi < 8; mi++) {
        CP_WAIT(0);
        __syncthreads();

        float acc[2][8][4];
        #pragma unroll
        for (int i = 0; i < 2; i++)
            #pragma unroll
            for (int j = 0; j < 8; j++)
                #pragma unroll
                for (int q = 0; q < 4; q++) acc[i][j][q] = 0.f;

        #pragma unroll
        for (int ks = 0; ks < 8; ks++) {
            uint32_t a[2][4], b[4][4];
            #pragma unroll
            for (int ai = 0; ai < 2; ai++)
                ldmx4(a[ai], sbQ + SWZ(wn * 32 + ai * 16 + (lane & 15), 2 * ks + (lane >> 4)));
            #pragma unroll
            for (int bi = 0; bi < 4; bi++)
                ldmx4(b[bi], sbK + SWZ(wm * 64 + bi * 16 + (lane & 7) + ((lane >> 4) << 3),
                                       2 * ks + ((lane >> 3) & 1)));
            #pragma unroll
            for (int ai = 0; ai < 2; ai++)
                #pragma unroll
                for (int bi = 0; bi < 4; bi++) {
                    mma16816(acc[ai][2 * bi],     a[ai], b[bi][0], b[bi][1]);
                    mma16816(acc[ai][2 * bi + 1], a[ai], b[bi][2], b[bi][3]);
                }
        }
        __syncthreads();            // all warps done reading K

        // prefetch next K (overlaps the epilogue below)
        if (mi + 1 < 8) {
            int mn = mg + (mi + 1) * 128;
            #pragma unroll
            for (int it = 0; it < 16; it++) {
                int row = lrow + it * 8;
                CP_ASYNC16(sbK + SWZ(row, lch), Kp + (size_t)(mn + row) * CDIM + lch * 8);
            }
        }
        CP_COMMIT();

        // epilogue: exp -> bf16x2 fragment units -> coalesced STG.64, per njp
        int m0 = mg + mi * 128;
        int m8pb = (m0 >> 4) + wm * 4;           // m8-pair base for this warp
        float* pp = g_psum + ((size_t)bl * NTILES + slot) * NDIM + m0 + wm * 64;

        #pragma unroll
        for (int njp = 0; njp < 4; njp++) {
            float s00 = 0.f, s01 = 0.f, s10 = 0.f, s11 = 0.f;
            #pragma unroll
            for (int ai = 0; ai < 2; ai++) {
                size_t n8 = (size_t)(n0 >> 3) + wn * 4 + ai * 2;
                float e0[4], e1[4];
                #pragma unroll
                for (int q = 0; q < 4; q++) {
                    e0[q] = ex2f(acc[ai][2 * njp][q] * EXC);
                    e1[q] = ex2f(acc[ai][2 * njp + 1][q] * EXC);
                }
                s00 += e0[0] + e0[2]; s01 += e0[1] + e0[3];
                s10 += e1[0] + e1[2]; s11 += e1[1] + e1[3];
                uint2 v0, v1;
                v0.x = packbf(e0[0], e0[1]); v0.y = packbf(e1[0], e1[1]);   // rows gid
                v1.x = packbf(e0[2], e0[3]); v1.y = packbf(e1[2], e1[3]);   // rows gid+8
                size_t i0 = ((((size_t)bl * 512 + n8) * 256) + m8pb + njp) * 64 + lane * 2;
                *(uint2*)&g_Sf[i0] = v0;
                *(uint2*)&g_Sf[i0 + 256 * 64] = v1;                          // n8+1
            }
            #pragma unroll
            for (int off = 4; off < 32; off <<= 1) {
                s00 += __shfl_xor_sync(0xffffffffu, s00, off);
                s01 += __shfl_xor_sync(0xffffffffu, s01, off);
                s10 += __shfl_xor_sync(0xffffffffu, s10, off);
                s11 += __shfl_xor_sync(0xffffffffu, s11, off);
            }
            if (lane < 4) {
                pp[njp * 16 + 2 * tig]         = s00;
                pp[njp * 16 + 2 * tig + 1]     = s01;
                pp[njp * 16 + 8 + 2 * tig]     = s10;
                pp[njp * 16 + 8 + 2 * tig + 1] = s11;
            }
        }
    }
}

// ---------------- kernel 3: alpha = 1/Z, fold into Gt ------------------------
__global__ void statscale_kernel()
{
    int bl = blockIdx.y;
    int m = blockIdx.x * 128 + threadIdx.x;
    const float* ps = g_psum + (size_t)bl * NTILES * NDIM + m;
    float Z = 0.f;
    #pragma unroll 8
    for (int t = 0; t < NTILES; t++) Z += ps[(size_t)t * NDIM];
    float al = 1.f / Z;
    __nv_bfloat16* G = g_Gt + (size_t)bl * CDIM * NDIM + m;
    #pragma unroll 4
    for (int c = 0; c < CDIM; c++) {
        float v = __bfloat162float(G[(size_t)c * NDIM]);
        G[(size_t)c * NDIM] = __float2bfloat16(v * al);
    }
}

// ---------------- kernel 4: acc[c][n] = sum_m Gta[c][m] * e[n][m] ------------
// B read directly as fragment units (LDS.64), A via ldmatrix.
#define KC 64
#define NC 32
#define STG_BYTES 32768
#define SMEM_ATT (3 * STG_BYTES)
__global__ __launch_bounds__(256, 2) void attnout_kernel()
{
    extern __shared__ char sm[];
    uint32_t sb = smem_u32(sm);

    int tid = threadIdx.x, lane = tid & 31, w = tid >> 5;
    int wc = w >> 2, wn = w & 3;                 // 2(c) x 4(n) warp grid
    int bl = blockIdx.y, n0 = blockIdx.x * 128;
    int mbase = blockIdx.z * 2048;
    int n08 = n0 >> 3;

    const __nv_bfloat16* Gp = g_Gt + (size_t)bl * CDIM * NDIM;

    int lrow = tid >> 3, lch = tid & 7;

    #pragma unroll
    for (int p = 0; p < 3; p++) {
        int mq = mbase + p * KC;
        uint32_t sA = sb + p * STG_BYTES, sB = sA + 16384;
        #pragma unroll
        for (int it = 0; it < 4; it++) {
            int row = lrow + it * 32;
            CP_ASYNC16(sA + SWZ8(row, lch), Gp + (size_t)row * NDIM + mq + lch * 8);
        }
        int mq16 = mq >> 4;
        #pragma unroll
        for (int it = 0; it < 4; it++) {
            int tp = tid + it * 256;
            int n8l = tp >> 6, inner = tp & 63;
            const uint32_t* src = g_Sf + (((size_t)bl * 512 + n08 + n8l) * 256 + mq16) * 64 + inner * 4;
            CP_ASYNC16(sB + tp * 16, src);
        }
        CP_COMMIT();
    }

    float acc[4][4][4];
    #pragma unroll
    for (int i = 0; i < 4; i++)
        #pragma unroll
        for (int j = 0; j < 4; j++)
            #pragma unroll
            for (int q = 0; q < 4; q++) acc[i][j][q] = 0.f;

    int st = 0;
    for (int chk = 0; chk < NC; chk++) {
        CP_WAIT(2);
        __syncthreads();

        uint32_t sA = sb + st * STG_BYTES, sB = sA + 16384;
        #pragma unroll
        for (int ks = 0; ks < 4; ks++) {
            uint32_t a[4][4], b0[4], b1[4];
            #pragma unroll
            for (int mi = 0; mi < 4; mi++)
                ldmx4(a[mi], sA + SWZ8(wc * 64 + mi * 16 + (lane & 15), 2 * ks + (lane >> 4)));
            #pragma unroll
            for (int u = 0; u < 4; u++)
                lds64(b0[u], b1[u], sB + ((((wn * 4 + u) * 4 + ks) * 32 + lane) << 3));
            #pragma unroll
            for (int mi = 0; mi < 4; mi++)
                #pragma unroll
                for (int u = 0; u < 4; u++)
                    mma16816(acc[mi][u], a[mi], b0[u], b1[u]);
        }
        __syncthreads();

        if (chk + 3 < NC) {
            int mq = mbase + (chk + 3) * KC;
            #pragma unroll
            for (int it = 0; it < 4; it++) {
                int row = lrow + it * 32;
                CP_ASYNC16(sA + SWZ8(row, lch), Gp + (size_t)row * NDIM + mq + lch * 8);
            }
            int mq16 = mq >> 4;
            #pragma unroll
            for (int it = 0; it < 4; it++) {
                int tp = tid + it * 256;
                int n8l = tp >> 6, inner = tp & 63;
                const uint32_t* src = g_Sf + (((size_t)bl * 512 + n08 + n8l) * 256 + mq16) * 64 + inner * 4;
                CP_ASYNC16(sB + tp * 16, src);
            }
        }
        CP_COMMIT();
        st = (st + 1 == 3) ? 0 : st + 1;
    }

    int gid = lane >> 2, tig = lane & 3;
    float* dstb = g_acc + ((size_t)(bl * 2 + blockIdx.z)) * CDIM * NDIM;
    #pragma unroll
    for (int mi = 0; mi < 4; mi++) {
        int c0 = wc * 64 + mi * 16 + gid;
        #pragma unroll
        for (int nj = 0; nj < 4; nj++) {
            int n = n0 + wn * 32 + nj * 8 + 2 * tig;
            *(float2*)(dstb + (size_t)c0 * NDIM + n)       = make_float2(acc[mi][nj][0], acc[mi][nj][1]);
            *(float2*)(dstb + (size_t)(c0 + 8) * NDIM + n) = make_float2(acc[mi][nj][2], acc[mi][nj][3]);
        }
    }
}

// ---------------- kernel 5: out = x + mean_l(acc) ---------------------------
__global__ void epilogue_kernel(const float* __restrict__ X, float* __restrict__ out)
{
    size_t idx = (size_t)blockIdx.x * blockDim.x + threadIdx.x;
    const size_t total = (size_t)BDIM * CDIM * NDIM;
    if (idx >= total) return;
    size_t b   = idx / ((size_t)CDIM * NDIM);
    size_t rem = idx % ((size_t)CDIM * NDIM);
    float s = 0.f;
    #pragma unroll
    for (int l = 0; l < LNUM; l++) {
        size_t base = ((size_t)(b * LNUM + l) * 2) * CDIM * NDIM;
        s += g_acc[base + rem] + g_acc[base + (size_t)CDIM * NDIM + rem];
    }
    out[idx] = X[idx] + s * (1.0f / LNUM);
}

// ---------------- launch -----------------------------------------------------
extern "C" void kernel_launch(void* const* d_in, const int* in_sizes, int n_in,
                              void* d_out, int out_size)
{
    const float* x  = (const float*)d_in[0];
    const float* W1 = (const float*)d_in[1];
    const float* b1 = (const float*)d_in[2];
    const float* W2 = (const float*)d_in[3];
    const float* b2 = (const float*)d_in[4];
    const float* Wg = (const float*)d_in[5];
    const float* bg = (const float*)d_in[6];
    float* out = (float*)d_out;

    cudaFuncSetAttribute(projmma_kernel, cudaFuncAttributeMaxDynamicSharedMemorySize, SMEM_PROJ);
    cudaFuncSetAttribute(score_kernel,   cudaFuncAttributeMaxDynamicSharedMemorySize, SMEM_SCORE);
    cudaFuncSetAttribute(attnout_kernel, cudaFuncAttributeMaxDynamicSharedMemorySize, SMEM_ATT);

    xt_kernel<<<dim3(NDIM / 32, CDIM / 32, BDIM), dim3(32, 8)>>>(x);
    wcvt_kernel<<<(3 * LNUM * CDIM * CDIM + 255) / 256, 256>>>(W1, W2, Wg);
    projmma_kernel<<<dim3(NT, 3, BL), 256, SMEM_PROJ>>>(b1, b2, bg);
    score_kernel<<<dim3(64, 4, BL), 128, SMEM_SCORE>>>();
    statscale_kernel<<<dim3(NDIM / 128, BL), 128>>>();
    attnout_kernel<<<dim3(NT, BL, 2), 256, SMEM_ATT>>>();
    epilogue_kernel<<<(unsigned)(((size_t)BDIM * CDIM * NDIM + 255) / 256), 256>>>(x, out);
}